// round 1
// baseline (speedup 1.0000x reference)
#include <cuda_runtime.h>
#include <math.h>

#define F_IN   128
#define G_HID  128
#define L_HID  64
#define G4     256   // 4*L_HID
#define N_CLS  8
#define PP     4
#define LSEQ   16
#define D_PATH 129
#define KTOT   193   // D_PATH + L_HID
#define CSTRIDE 196  // padded row stride for combined [x|h] smem tile
#define NMAX   20000
#define BMAX   (NMAX*PP)

// ---------------- scratch (static device globals; no runtime allocation) -----
__device__ float g_deg [NMAX];
__device__ float g_dinv[NMAX];
__device__ float g_xw  [NMAX*G_HID];
__device__ float g_g0  [NMAX*G_HID];
__device__ float g_Wt  [2*KTOT*G4];     // [dir][k][gate] transposed combined weights
__device__ float g_Bt  [2*G4];          // bih+bhh per dir
__device__ float g_hout[2*(size_t)BMAX*L_HID];
__device__ int   g_idx64;

// ---------------- small helpers ---------------------------------------------
__device__ __forceinline__ float sigf(float x){ return __fdividef(1.f, 1.f + __expf(-x)); }
__device__ __forceinline__ float tanhfast(float x){ return 2.f*sigf(2.f*x) - 1.f; }

__device__ __forceinline__ unsigned long long pk2(float v){
  unsigned long long r; unsigned int u = __float_as_uint(v);
  asm("mov.b64 %0, {%1,%2};" : "=l"(r) : "r"(u), "r"(u));
  return r;
}
__device__ __forceinline__ void fma2(unsigned long long &d, unsigned long long a, unsigned long long b){
  asm("fma.rn.f32x2 %0, %1, %2, %0;" : "+l"(d) : "l"(a), "l"(b));
}
__device__ __forceinline__ float2 upk(unsigned long long v){
  unsigned int lo, hi;
  asm("mov.b64 {%0,%1}, %2;" : "=r"(lo), "=r"(hi) : "l"(v));
  float2 f; f.x = __uint_as_float(lo); f.y = __uint_as_float(hi); return f;
}

// ---------------- edge-index dtype detection --------------------------------
__global__ void k_detect(const long long* __restrict__ e, int E){
  if (blockIdx.x == 0 && threadIdx.x == 0){
    int ok = 1;
    #pragma unroll
    for (int i = 0; i < 8; i++){
      long long v = e[i];
      if (v < 0 || v >= NMAX) ok = 0;
    }
    g_idx64 = ok;
  }
}

// ---------------- GCN --------------------------------------------------------
__global__ void k_deg_init(int n){
  int i = blockIdx.x*blockDim.x + threadIdx.x;
  if (i < n) g_deg[i] = 1.0f;   // self-loop weight
}

__global__ void k_deg_edges(const long long* __restrict__ e64,
                            const int* __restrict__ e32,
                            const float* __restrict__ ew, int E){
  int e = blockIdx.x*blockDim.x + threadIdx.x;
  if (e < E){
    int dst = g_idx64 ? (int)e64[(size_t)E + e] : e32[(size_t)E + e];
    atomicAdd(&g_deg[dst], ew[e]);
  }
}

__global__ void k_dinv(int n){
  int i = blockIdx.x*blockDim.x + threadIdx.x;
  if (i < n){
    float d = g_deg[i];
    g_dinv[i] = d > 0.f ? rsqrtf(d) : 0.f;
  }
}

// xw = X @ Wg  ([n,128] x [128,128])
__global__ void k_xw(const float* __restrict__ X, const float* __restrict__ Wg, int n){
  __shared__ float xs[16][128];
  int j  = threadIdx.x;          // 128 threads
  int r0 = blockIdx.x*16;
  #pragma unroll
  for (int r = 0; r < 16; r++){
    int row = r0 + r;
    xs[r][j] = (row < n) ? X[(size_t)row*F_IN + j] : 0.f;
  }
  __syncthreads();
  float acc[16];
  #pragma unroll
  for (int r = 0; r < 16; r++) acc[r] = 0.f;
  for (int k = 0; k < F_IN; k++){
    float w = Wg[(size_t)k*G_HID + j];
    #pragma unroll
    for (int r = 0; r < 16; r++) acc[r] = fmaf(xs[r][k], w, acc[r]);
  }
  #pragma unroll
  for (int r = 0; r < 16; r++){
    int row = r0 + r;
    if (row < n) g_xw[(size_t)row*G_HID + j] = acc[r];
  }
}

// self-loop term: g0 = dinv^2 * xw
__global__ void k_g0init(int n){
  int idx = blockIdx.x*blockDim.x + threadIdx.x;
  if (idx < n*G_HID){
    int ni = idx >> 7;
    float d = g_dinv[ni];
    g_g0[idx] = d*d*g_xw[idx];
  }
}

// edge aggregation: g0[dst] += dinv[src]*ew*dinv[dst] * xw[src]
__global__ void k_agg(const long long* __restrict__ e64,
                      const int* __restrict__ e32,
                      const float* __restrict__ ew, int E){
  int e    = blockIdx.x*8 + (threadIdx.x >> 5);
  int lane = threadIdx.x & 31;
  if (e < E){
    int src, dst;
    if (g_idx64){ src = (int)e64[e]; dst = (int)e64[(size_t)E + e]; }
    else        { src = e32[e];      dst = e32[(size_t)E + e]; }
    float nrm = g_dinv[src]*ew[e]*g_dinv[dst];
    const float* xr = g_xw + (size_t)src*G_HID;
    float*       gr = g_g0 + (size_t)dst*G_HID;
    #pragma unroll
    for (int f = 0; f < 4; f++)
      atomicAdd(&gr[lane + 32*f], nrm*xr[lane + 32*f]);
  }
}

// ---------------- LSTM weight prep: transpose into [dir][k:193][gate:256] ----
__global__ void k_wprep(const float* __restrict__ Wihf, const float* __restrict__ Whhf,
                        const float* __restrict__ bihf, const float* __restrict__ bhhf,
                        const float* __restrict__ Wihb, const float* __restrict__ Whhb,
                        const float* __restrict__ bihb, const float* __restrict__ bhhb){
  int idx = blockIdx.x*blockDim.x + threadIdx.x;
  const int tot = 2*KTOT*G4;
  if (idx < tot){
    int d   = idx / (KTOT*G4);
    int rem = idx - d*(KTOT*G4);
    int k = rem >> 8;
    int j = rem & 255;
    const float* Wih = d ? Wihb : Wihf;
    const float* Whh = d ? Whhb : Whhf;
    g_Wt[idx] = (k < D_PATH) ? Wih[(size_t)j*D_PATH + k]
                             : Whh[(size_t)j*L_HID + (k - D_PATH)];
  }
  if (idx < 2*G4){
    int d = idx >> 8, j = idx & 255;
    g_Bt[idx] = d ? (bihb[j] + bhhb[j]) : (bihf[j] + bhhf[j]);
  }
}

// ---------------- fused BiLSTM -----------------------------------------------
// block: 256 threads, 64 sequences, one direction (blockIdx.y).
// Per step: G[64,256] = [x_l | h][64,193] @ Wt[193,256] + bias, then cell update.
// Accumulation in packed f32x2 (2x FFMA throughput on sm_103a).
__device__ __forceinline__ void fma_row(unsigned long long (&acc)[4][8],
                                        const float* ar, int k,
                                        ulonglong2 q0, ulonglong2 q1,
                                        ulonglong2 q2, ulonglong2 q3){
  #pragma unroll
  for (int s = 0; s < 4; s++){
    unsigned long long a2 = pk2(ar[s*CSTRIDE + k]);
    fma2(acc[s][0], a2, q0.x); fma2(acc[s][1], a2, q0.y);
    fma2(acc[s][2], a2, q1.x); fma2(acc[s][3], a2, q1.y);
    fma2(acc[s][4], a2, q2.x); fma2(acc[s][5], a2, q2.y);
    fma2(acc[s][6], a2, q3.x); fma2(acc[s][7], a2, q3.y);
  }
}

__global__ void __launch_bounds__(256,2) k_lstm(const float* __restrict__ Cin, int B){
  extern __shared__ float sm[];
  float* gs  = sm;                 // [64*256] gate buffer; aliased as comb [64*CSTRIDE]
  float* hs  = sm + 64*256;        // [64*66]
  float* cs  = hs + 64*66;         // [64*66]
  float* bsh = cs + 64*66;         // [256]

  const int tid = threadIdx.x;
  const int tx  = tid & 15;        // 16-column group
  const int ty  = tid >> 4;        // 4-sequence group
  const int dir = blockIdx.y;
  const int b0  = blockIdx.x * 64;
  const float* Wc = g_Wt + (size_t)dir*(KTOT*G4) + tx*16;

  for (int i = tid; i < 64*66; i += 256){ hs[i] = 0.f; cs[i] = 0.f; }
  bsh[tid] = g_Bt[dir*G4 + tid];
  __syncthreads();

  for (int step = 0; step < LSEQ; ++step){
    const int l = dir ? (LSEQ-1-step) : step;

    // stage x_l and h into comb (row stride CSTRIDE)
    {
      const float* src = Cin + (size_t)b0*(LSEQ*D_PATH) + (size_t)l*D_PATH;
      for (int i = tid; i < 64*D_PATH; i += 256){
        int r = i / D_PATH, c = i - r*D_PATH;
        gs[r*CSTRIDE + c] = src[(size_t)r*(LSEQ*D_PATH) + c];
      }
      for (int i = tid; i < 64*L_HID; i += 256){
        int r = i >> 6, u = i & 63;
        gs[r*CSTRIDE + D_PATH + u] = hs[r*66 + u];
      }
    }
    __syncthreads();

    unsigned long long acc[4][8];
    #pragma unroll
    for (int s = 0; s < 4; s++)
      #pragma unroll
      for (int p = 0; p < 8; p++) acc[s][p] = 0ull;

    const float* ar = gs + (ty*4)*CSTRIDE;

    { // pipelined k-loop over 193 rows of Wt
      const ulonglong2* wp = (const ulonglong2*)Wc;
      ulonglong2 q0 = wp[0], q1 = wp[1], q2 = wp[2], q3 = wp[3];
      #pragma unroll 4
      for (int k = 0; k < KTOT-1; k++){
        const ulonglong2* np = (const ulonglong2*)(Wc + (size_t)(k+1)*G4);
        ulonglong2 n0 = np[0], n1 = np[1], n2 = np[2], n3 = np[3];
        fma_row(acc, ar, k, q0, q1, q2, q3);
        q0 = n0; q1 = n1; q2 = n2; q3 = n3;
      }
      fma_row(acc, ar, KTOT-1, q0, q1, q2, q3);
    }
    __syncthreads();   // comb fully consumed

    // write gates (+bias) into gs[64][256]
    {
      float bias_[16];
      #pragma unroll
      for (int q = 0; q < 16; q++) bias_[q] = bsh[tx*16 + q];
      #pragma unroll
      for (int s = 0; s < 4; s++){
        float* gp = gs + (ty*4 + s)*G4 + tx*16;
        #pragma unroll
        for (int p = 0; p < 4; p++){
          float2 f0 = upk(acc[s][2*p]);
          float2 f1 = upk(acc[s][2*p+1]);
          float4 o;
          o.x = f0.x + bias_[4*p+0];
          o.y = f0.y + bias_[4*p+1];
          o.z = f1.x + bias_[4*p+2];
          o.w = f1.y + bias_[4*p+3];
          ((float4*)gp)[p] = o;
        }
      }
    }
    __syncthreads();

    // elementwise cell update (gate order i,f,g,o)
    {
      const int q = tid >> 6;      // 0..3
      const int u = tid & 63;
      #pragma unroll
      for (int r = 0; r < 16; r++){
        int seq = r*4 + q;
        float gi = gs[seq*G4 +       u];
        float gf = gs[seq*G4 +  64 + u];
        float gg = gs[seq*G4 + 128 + u];
        float go = gs[seq*G4 + 192 + u];
        float c  = sigf(gf)*cs[seq*66 + u] + sigf(gi)*tanhfast(gg);
        cs[seq*66 + u] = c;
        hs[seq*66 + u] = sigf(go)*tanhfast(c);
      }
    }
    __syncthreads();
  }

  for (int i = tid; i < 64*64; i += 256){
    int r = i >> 6, u = i & 63;
    g_hout[(size_t)dir*B*L_HID + (size_t)(b0 + r)*L_HID + u] = hs[r*66 + u];
  }
}

// ---------------- final fuse: out = [relu(g0+bg) | mean_p(hf|hb)] @ Wf + bf --
__global__ void k_fuse(const float* __restrict__ bg, const float* __restrict__ Wf,
                       const float* __restrict__ bf, float* __restrict__ out,
                       int N, int B){
  __shared__ float v[256];
  int n = blockIdx.x;
  int t = threadIdx.x;
  float val;
  if (t < 128){
    val = g_g0[(size_t)n*G_HID + t] + bg[t];
    val = val > 0.f ? val : 0.f;
  } else if (t < 192){
    int u = t - 128;
    const float* hf = g_hout + (size_t)(n*PP)*L_HID + u;
    val = 0.25f*(hf[0] + hf[L_HID] + hf[2*L_HID] + hf[3*L_HID]);
  } else {
    int u = t - 192;
    const float* hb = g_hout + (size_t)B*L_HID + (size_t)(n*PP)*L_HID + u;
    val = 0.25f*(hb[0] + hb[L_HID] + hb[2*L_HID] + hb[3*L_HID]);
  }
  v[t] = val;
  __syncthreads();
  int c = t >> 5, lane = t & 31;
  float s = 0.f;
  for (int k = lane; k < 256; k += 32) s += v[k]*Wf[(size_t)k*N_CLS + c];
  #pragma unroll
  for (int off = 16; off; off >>= 1) s += __shfl_down_sync(0xffffffffu, s, off);
  if (lane == 0) out[(size_t)n*N_CLS + c] = s + bf[c];
}

// ---------------- launch ------------------------------------------------------
extern "C" void kernel_launch(void* const* d_in, const int* in_sizes, int n_in,
                              void* d_out, int out_size){
  const float*     X    = (const float*)d_in[0];
  const long long* EI64 = (const long long*)d_in[1];
  const int*       EI32 = (const int*)d_in[1];
  const float*     EW   = (const float*)d_in[2];
  const float*     C    = (const float*)d_in[3];
  const float*     Wg   = (const float*)d_in[4];
  const float*     bg   = (const float*)d_in[5];
  const float*     Wihf = (const float*)d_in[6];
  const float*     Whhf = (const float*)d_in[7];
  const float*     bihf = (const float*)d_in[8];
  const float*     bhhf = (const float*)d_in[9];
  const float*     Wihb = (const float*)d_in[10];
  const float*     Whhb = (const float*)d_in[11];
  const float*     bihb = (const float*)d_in[12];
  const float*     bhhb = (const float*)d_in[13];
  const float*     Wf   = (const float*)d_in[14];
  const float*     bf   = (const float*)d_in[15];
  float* out = (float*)d_out;

  const int N = in_sizes[0] / F_IN;
  const int E = in_sizes[1] / 2;
  const int B = N * PP;

  const int lstm_smem = (64*256 + 64*66 + 64*66 + 256) * (int)sizeof(float); // 100352
  cudaFuncSetAttribute(k_lstm, cudaFuncAttributeMaxDynamicSharedMemorySize, lstm_smem);

  k_detect   <<<1, 32>>>(EI64, E);
  k_deg_init <<<(N + 255)/256, 256>>>(N);
  k_deg_edges<<<(E + 255)/256, 256>>>(EI64, EI32, EW, E);
  k_dinv     <<<(N + 255)/256, 256>>>(N);
  k_xw       <<<(N + 15)/16, 128>>>(X, Wg, N);
  k_g0init   <<<(N*G_HID + 255)/256, 256>>>(N);
  k_agg      <<<(E + 7)/8, 256>>>(EI64, EI32, EW, E);
  k_wprep    <<<(2*KTOT*G4 + 255)/256, 256>>>(Wihf, Whhf, bihf, bhhf,
                                              Wihb, Whhb, bihb, bhhb);
  dim3 lgrid(B/64, 2);
  k_lstm     <<<lgrid, 256, lstm_smem>>>(C, B);
  k_fuse     <<<N, 256>>>(bg, Wf, bf, out, N, B);
}

// round 2
// speedup vs baseline: 2.2933x; 2.2933x over previous
#include <cuda_runtime.h>
#include <math.h>

#define F_IN   128
#define G_HID  128
#define L_HID  64
#define G4     256   // 4*L_HID
#define N_CLS  8
#define PP     4
#define LSEQ   16
#define D_PATH 129
#define KTOT   193   // D_PATH + L_HID
#define CST    197   // padded comb row stride (odd mod-32 -> conflict-free staging)
#define KC     24    // weight k-chunk rows staged in smem
#define NCH    8     // 8*24 = 192 full rows, +1 remainder
#define NMAX   20000
#define BMAX   (NMAX*PP)

typedef unsigned long long ull;

// ---------------- scratch (static device globals; no runtime allocation) -----
__device__ float g_deg [NMAX];
__device__ float g_dinv[NMAX];
__device__ float g_xw  [NMAX*G_HID];
__device__ float g_g0  [NMAX*G_HID];
__device__ float g_Wt  [2*KTOT*G4];     // [dir][k][gate] transposed combined weights
__device__ float g_Bt  [2*G4];          // bih+bhh per dir
__device__ float g_hout[2*(size_t)BMAX*L_HID];
__device__ int   g_idx64;

// ---------------- small helpers ---------------------------------------------
__device__ __forceinline__ float sigf(float x){ return __fdividef(1.f, 1.f + __expf(-x)); }
__device__ __forceinline__ float tanhfast(float x){ return 2.f*sigf(2.f*x) - 1.f; }

__device__ __forceinline__ ull pk2(float v){
  ull r; unsigned int u = __float_as_uint(v);
  asm("mov.b64 %0, {%1,%2};" : "=l"(r) : "r"(u), "r"(u));
  return r;
}
__device__ __forceinline__ void fma2(ull &d, ull a, ull b){
  asm("fma.rn.f32x2 %0, %1, %2, %0;" : "+l"(d) : "l"(a), "l"(b));
}
__device__ __forceinline__ float2 upk(ull v){
  unsigned int lo, hi;
  asm("mov.b64 {%0,%1}, %2;" : "=r"(lo), "=r"(hi) : "l"(v));
  float2 f; f.x = __uint_as_float(lo); f.y = __uint_as_float(hi); return f;
}

// ---------------- edge-index dtype detection --------------------------------
__global__ void k_detect(const long long* __restrict__ e, int E){
  if (blockIdx.x == 0 && threadIdx.x == 0){
    int ok = 1;
    #pragma unroll
    for (int i = 0; i < 8; i++){
      long long v = e[i];
      if (v < 0 || v >= NMAX) ok = 0;
    }
    g_idx64 = ok;
  }
}

// ---------------- GCN --------------------------------------------------------
__global__ void k_deg_init(int n){
  int i = blockIdx.x*blockDim.x + threadIdx.x;
  if (i < n) g_deg[i] = 1.0f;   // self-loop weight
}

__global__ void k_deg_edges(const long long* __restrict__ e64,
                            const int* __restrict__ e32,
                            const float* __restrict__ ew, int E){
  int e = blockIdx.x*blockDim.x + threadIdx.x;
  if (e < E){
    int dst = g_idx64 ? (int)e64[(size_t)E + e] : e32[(size_t)E + e];
    atomicAdd(&g_deg[dst], ew[e]);
  }
}

__global__ void k_dinv(int n){
  int i = blockIdx.x*blockDim.x + threadIdx.x;
  if (i < n){
    float d = g_deg[i];
    g_dinv[i] = d > 0.f ? rsqrtf(d) : 0.f;
  }
}

// xw = X @ Wg  ([n,128] x [128,128])
__global__ void k_xw(const float* __restrict__ X, const float* __restrict__ Wg, int n){
  __shared__ float xs[16][128];
  int j  = threadIdx.x;          // 128 threads
  int r0 = blockIdx.x*16;
  #pragma unroll
  for (int r = 0; r < 16; r++){
    int row = r0 + r;
    xs[r][j] = (row < n) ? X[(size_t)row*F_IN + j] : 0.f;
  }
  __syncthreads();
  float acc[16];
  #pragma unroll
  for (int r = 0; r < 16; r++) acc[r] = 0.f;
  for (int k = 0; k < F_IN; k++){
    float w = Wg[(size_t)k*G_HID + j];
    #pragma unroll
    for (int r = 0; r < 16; r++) acc[r] = fmaf(xs[r][k], w, acc[r]);
  }
  #pragma unroll
  for (int r = 0; r < 16; r++){
    int row = r0 + r;
    if (row < n) g_xw[(size_t)row*G_HID + j] = acc[r];
  }
}

// self-loop term: g0 = dinv^2 * xw
__global__ void k_g0init(int n){
  int idx = blockIdx.x*blockDim.x + threadIdx.x;
  if (idx < n*G_HID){
    int ni = idx >> 7;
    float d = g_dinv[ni];
    g_g0[idx] = d*d*g_xw[idx];
  }
}

// edge aggregation: g0[dst] += dinv[src]*ew*dinv[dst] * xw[src]
__global__ void k_agg(const long long* __restrict__ e64,
                      const int* __restrict__ e32,
                      const float* __restrict__ ew, int E){
  int e    = blockIdx.x*8 + (threadIdx.x >> 5);
  int lane = threadIdx.x & 31;
  if (e < E){
    int src, dst;
    if (g_idx64){ src = (int)e64[e]; dst = (int)e64[(size_t)E + e]; }
    else        { src = e32[e];      dst = e32[(size_t)E + e]; }
    float nrm = g_dinv[src]*ew[e]*g_dinv[dst];
    const float4* xr = (const float4*)(g_xw + (size_t)src*G_HID);
    float*        gr = g_g0 + (size_t)dst*G_HID;
    float4 v = xr[lane];
    atomicAdd(&gr[lane*4+0], nrm*v.x);
    atomicAdd(&gr[lane*4+1], nrm*v.y);
    atomicAdd(&gr[lane*4+2], nrm*v.z);
    atomicAdd(&gr[lane*4+3], nrm*v.w);
  }
}

// ---------------- LSTM weight prep: transpose into [dir][k:193][gate:256] ----
__global__ void k_wprep(const float* __restrict__ Wihf, const float* __restrict__ Whhf,
                        const float* __restrict__ bihf, const float* __restrict__ bhhf,
                        const float* __restrict__ Wihb, const float* __restrict__ Whhb,
                        const float* __restrict__ bihb, const float* __restrict__ bhhb){
  int idx = blockIdx.x*blockDim.x + threadIdx.x;
  const int tot = 2*KTOT*G4;
  if (idx < tot){
    int d   = idx / (KTOT*G4);
    int rem = idx - d*(KTOT*G4);
    int k = rem >> 8;
    int j = rem & 255;
    const float* Wih = d ? Wihb : Wihf;
    const float* Whh = d ? Whhb : Whhf;
    g_Wt[idx] = (k < D_PATH) ? Wih[(size_t)j*D_PATH + k]
                             : Whh[(size_t)j*L_HID + (k - D_PATH)];
  }
  if (idx < 2*G4){
    int d = idx >> 8, j = idx & 255;
    g_Bt[idx] = d ? (bihb[j] + bhhb[j]) : (bihf[j] + bhhf[j]);
  }
}

// ---------------- fused BiLSTM -----------------------------------------------
// block: 512 threads, 128 sequences, one direction (blockIdx.y), 1 block/SM.
// Per step: G[128,256] = [x_l | h][128,193] @ Wt[193,256] + bias, cell update.
// Weights staged in smem per k-chunk (block reads tile ONCE per step).
// warp = one 8-seq group  -> activation LDS fully uniform (broadcast);
// 32 column-groups of 8   -> weight LDS.128 conflict-free.
__global__ void __launch_bounds__(512,1) k_lstm(const float* __restrict__ Cin, int B){
  extern __shared__ float sm[];
  float* gs   = sm;               // alias: comb [128][CST] / gates [128][256]
  float* hs   = sm + 128*256;     // [128][64]
  float* cs   = hs + 128*64;      // [128][64]
  float* wbuf = cs + 128*64;      // [KC][256]
  float* bsh  = wbuf + KC*256;    // [256]

  const int tid = threadIdx.x;
  const int tx  = tid & 31;       // column group: cols tx*8 .. tx*8+7
  const int ty  = tid >> 5;       // seq group: seqs ty*8 .. ty*8+7
  const int dir = blockIdx.y;
  const int b0  = blockIdx.x * 128;
  const float* Wd = g_Wt + (size_t)dir*(KTOT*G4);

  for (int i = tid; i < 128*64; i += 512){ hs[i] = 0.f; cs[i] = 0.f; }
  if (tid < 256) bsh[tid] = g_Bt[dir*G4 + tid];
  __syncthreads();

  for (int step = 0; step < LSEQ; ++step){
    const int l = dir ? (LSEQ-1-step) : step;

    // ---- stage x_l and h into comb (row stride CST) ----
    {
      const float* src = Cin + (size_t)b0*(LSEQ*D_PATH) + (size_t)l*D_PATH;
      for (int i = tid; i < 128*D_PATH; i += 512){
        int r = i / D_PATH, c = i - r*D_PATH;
        gs[r*CST + c] = src[(size_t)r*(LSEQ*D_PATH) + c];
      }
      for (int i = tid; i < 128*64; i += 512){
        int r = i >> 6, u = i & 63;
        gs[r*CST + D_PATH + u] = hs[i];
      }
    }

    ull acc[8][4];
    #pragma unroll
    for (int s = 0; s < 8; s++)
      #pragma unroll
      for (int p = 0; p < 4; p++) acc[s][p] = 0ull;

    const float* ar = gs + (ty*8)*CST;

    // ---- k-chunks: stage KC rows of Wt in smem, FMA over chunk ----
    #pragma unroll 1
    for (int ch = 0; ch < NCH; ch++){
      __syncthreads();                       // staging done / prev chunk consumed
      {
        const float4* s4 = (const float4*)(Wd + (size_t)ch*KC*256);
        float4* d4 = (float4*)wbuf;
        d4[tid]        = s4[tid];
        d4[tid + 512]  = s4[tid + 512];
        d4[tid + 1024] = s4[tid + 1024];
      }
      __syncthreads();
      const int kb = ch*KC;
      #pragma unroll
      for (int kk = 0; kk < KC; kk++){
        const ulonglong2* w = (const ulonglong2*)(wbuf + kk*256 + tx*8);
        ulonglong2 w0 = w[0], w1 = w[1];
        #pragma unroll
        for (int s = 0; s < 8; s++){
          ull a2 = pk2(ar[s*CST + kb + kk]);
          fma2(acc[s][0], a2, w0.x);
          fma2(acc[s][1], a2, w0.y);
          fma2(acc[s][2], a2, w1.x);
          fma2(acc[s][3], a2, w1.y);
        }
      }
    }
    // remainder row k = 192
    __syncthreads();
    if (tid < 64) ((float4*)wbuf)[tid] = ((const float4*)(Wd + (size_t)192*256))[tid];
    __syncthreads();
    {
      const ulonglong2* w = (const ulonglong2*)(wbuf + tx*8);
      ulonglong2 w0 = w[0], w1 = w[1];
      #pragma unroll
      for (int s = 0; s < 8; s++){
        ull a2 = pk2(ar[s*CST + 192]);
        fma2(acc[s][0], a2, w0.x);
        fma2(acc[s][1], a2, w0.y);
        fma2(acc[s][2], a2, w1.x);
        fma2(acc[s][3], a2, w1.y);
      }
    }
    __syncthreads();   // all comb reads done before gates overwrite alias

    // ---- write gates (+bias) into gs[128][256] ----
    {
      float bb[8];
      #pragma unroll
      for (int q = 0; q < 8; q++) bb[q] = bsh[tx*8 + q];
      #pragma unroll
      for (int s = 0; s < 8; s++){
        float* gp = gs + (ty*8 + s)*G4 + tx*8;
        float2 f0 = upk(acc[s][0]);
        float2 f1 = upk(acc[s][1]);
        float2 f2 = upk(acc[s][2]);
        float2 f3 = upk(acc[s][3]);
        float4 o0; o0.x = f0.x+bb[0]; o0.y = f0.y+bb[1]; o0.z = f1.x+bb[2]; o0.w = f1.y+bb[3];
        float4 o1; o1.x = f2.x+bb[4]; o1.y = f2.y+bb[5]; o1.z = f3.x+bb[6]; o1.w = f3.y+bb[7];
        ((float4*)gp)[0] = o0;
        ((float4*)gp)[1] = o1;
      }
    }
    __syncthreads();

    // ---- elementwise cell update (gate order i,f,g,o) ----
    {
      const int q = tid >> 6;      // 0..7
      const int u = tid & 63;
      #pragma unroll
      for (int r = 0; r < 16; r++){
        int seq = r*8 + q;
        float gi = gs[seq*G4 +       u];
        float gf = gs[seq*G4 +  64 + u];
        float gg = gs[seq*G4 + 128 + u];
        float go = gs[seq*G4 + 192 + u];
        float c  = sigf(gf)*cs[seq*64 + u] + sigf(gi)*tanhfast(gg);
        cs[seq*64 + u] = c;
        hs[seq*64 + u] = sigf(go)*tanhfast(c);
      }
    }
    __syncthreads();
  }

  for (int i = tid; i < 128*64; i += 512){
    int r = i >> 6, u = i & 63;
    g_hout[(size_t)dir*B*L_HID + (size_t)(b0 + r)*L_HID + u] = hs[i];
  }
}

// ---------------- final fuse: out = [relu(g0+bg) | mean_p(hf|hb)] @ Wf + bf --
__global__ void k_fuse(const float* __restrict__ bg, const float* __restrict__ Wf,
                       const float* __restrict__ bf, float* __restrict__ out,
                       int N, int B){
  __shared__ float v[256];
  int n = blockIdx.x;
  int t = threadIdx.x;
  float val;
  if (t < 128){
    val = g_g0[(size_t)n*G_HID + t] + bg[t];
    val = val > 0.f ? val : 0.f;
  } else if (t < 192){
    int u = t - 128;
    const float* hf = g_hout + (size_t)(n*PP)*L_HID + u;
    val = 0.25f*(hf[0] + hf[L_HID] + hf[2*L_HID] + hf[3*L_HID]);
  } else {
    int u = t - 192;
    const float* hb = g_hout + (size_t)B*L_HID + (size_t)(n*PP)*L_HID + u;
    val = 0.25f*(hb[0] + hb[L_HID] + hb[2*L_HID] + hb[3*L_HID]);
  }
  v[t] = val;
  __syncthreads();
  int c = t >> 5, lane = t & 31;
  float s = 0.f;
  for (int k = lane; k < 256; k += 32) s += v[k]*Wf[(size_t)k*N_CLS + c];
  #pragma unroll
  for (int off = 16; off; off >>= 1) s += __shfl_down_sync(0xffffffffu, s, off);
  if (lane == 0) out[(size_t)n*N_CLS + c] = s + bf[c];
}

// ---------------- launch ------------------------------------------------------
extern "C" void kernel_launch(void* const* d_in, const int* in_sizes, int n_in,
                              void* d_out, int out_size){
  const float*     X    = (const float*)d_in[0];
  const long long* EI64 = (const long long*)d_in[1];
  const int*       EI32 = (const int*)d_in[1];
  const float*     EW   = (const float*)d_in[2];
  const float*     C    = (const float*)d_in[3];
  const float*     Wg   = (const float*)d_in[4];
  const float*     bg   = (const float*)d_in[5];
  const float*     Wihf = (const float*)d_in[6];
  const float*     Whhf = (const float*)d_in[7];
  const float*     bihf = (const float*)d_in[8];
  const float*     bhhf = (const float*)d_in[9];
  const float*     Wihb = (const float*)d_in[10];
  const float*     Whhb = (const float*)d_in[11];
  const float*     bihb = (const float*)d_in[12];
  const float*     bhhb = (const float*)d_in[13];
  const float*     Wf   = (const float*)d_in[14];
  const float*     bf   = (const float*)d_in[15];
  float* out = (float*)d_out;

  const int N = in_sizes[0] / F_IN;
  const int E = in_sizes[1] / 2;
  const int B = N * PP;

  const int lstm_smem = (128*256 + 128*64 + 128*64 + KC*256 + 256) * (int)sizeof(float); // 222208
  cudaFuncSetAttribute(k_lstm, cudaFuncAttributeMaxDynamicSharedMemorySize, lstm_smem);

  k_detect   <<<1, 32>>>(EI64, E);
  k_deg_init <<<(N + 255)/256, 256>>>(N);
  k_deg_edges<<<(E + 255)/256, 256>>>(EI64, EI32, EW, E);
  k_dinv     <<<(N + 255)/256, 256>>>(N);
  k_xw       <<<(N + 15)/16, 128>>>(X, Wg, N);
  k_g0init   <<<(N*G_HID + 255)/256, 256>>>(N);
  k_agg      <<<(E + 7)/8, 256>>>(EI64, EI32, EW, E);
  k_wprep    <<<(2*KTOT*G4 + 255)/256, 256>>>(Wihf, Whhf, bihf, bhhf,
                                              Wihb, Whhb, bihb, bhhb);
  dim3 lgrid(B/128, 2);
  k_lstm     <<<lgrid, 512, lstm_smem>>>(C, B);
  k_fuse     <<<N, 256>>>(bg, Wf, bf, out, N, B);
}